// round 7
// baseline (speedup 1.0000x reference)
#include <cuda_runtime.h>
#include <mma.h>
#include <math.h>
#include <stdint.h>

using namespace nvcuda;

// ===========================================================================
// AdaptiveFeaturePropagation, round 7: tf32 mma.sync (HMMA) implicit-GEMM.
// tcgen05 is unavailable (harness lowers via virtual arch compute_103, which
// rejects all "a"-features) -> use portable wmma m16n16k8 tf32 instead.
//   upsample(pad) -> conv_reduce[wmma] -> conv2[wmma] -> conv3+softmax -> svc
// 3x3 convs = 9 shifted 1x1 GEMMs over zero-padded planes (pads stay zero
// from static init; never written).
// ===========================================================================

static constexpr int HH = 129, WW = 129, HWP = HH * WW;   // 16641
static constexpr int PH = 131;                            // padded row width
static constexpr int PHW = PH * PH;                       // 17161
static constexpr int PLANE = 17568;                       // padded plane + guards
static constexpr int GUARD = 132;                         // lead guard
static constexpr int MT = 135;                            // ceil(17161/128)

__device__ float g_up_pad [4 * 128 * PLANE];  // padded upsampled low feats
__device__ float g_red_pad[2 * 512 * PLANE];  // padded relu(conv_reduce) concat
__device__ float g_c2  [2 * 256 * HWP];       // relu(conv2), unpadded
__device__ float g_kern[2 * 49  * HWP];       // softmax kernels
__device__ float g_w1T [9 * 256 * 128];       // w_reduce as [tap][oc][ci]
__device__ float g_w2T [9 * 256 * 512];       // w_conv2  as [tap][oc][ci]

__device__ __forceinline__ float f2tf32(float v) {
    float r;
    asm("cvt.rna.tf32.f32 %0, %1;" : "=f"(r) : "f"(v));
    return r;
}

// ---------------------------------------------------------------------------
// 1) Bilinear upsample into padded layout (pads remain statically-zero)
// ---------------------------------------------------------------------------
__global__ __launch_bounds__(256)
void upsample_kernel(const float* __restrict__ cur, const float* __restrict__ key)
{
    int idx = blockIdx.x * 256 + threadIdx.x;
    if (idx >= 4 * 128 * HWP) return;
    int slot = idx / (128 * HWP);
    int rem  = idx - slot * (128 * HWP);
    int c    = rem / HWP;
    int p    = rem - c * HWP;
    int Y = p / WW, X = p - Y * WW;
    int frame = slot & 1, b = slot >> 1;
    const float* src = (frame ? key : cur) + (b * 128 + c) * (33 * 33);

    const float s = 33.0f / 129.0f;
    float fy = (Y + 0.5f) * s - 0.5f;
    float fx = (X + 0.5f) * s - 0.5f;
    float y0f = floorf(fy), x0f = floorf(fx);
    float wy = fy - y0f, wx = fx - x0f;
    int y0 = (int)y0f, x0 = (int)x0f;
    int y0c = max(y0, 0), y1c = min(y0 + 1, 32);
    int x0c = max(x0, 0), x1c = min(x0 + 1, 32);

    float v00 = src[y0c * 33 + x0c], v01 = src[y0c * 33 + x1c];
    float v10 = src[y1c * 33 + x0c], v11 = src[y1c * 33 + x1c];
    float v0 = v00 + (v01 - v00) * wx;
    float v1 = v10 + (v11 - v10) * wx;
    g_up_pad[(size_t)slot * (128 * PLANE) + (size_t)c * PLANE
             + GUARD + (Y + 1) * PH + (X + 1)] = v0 + (v1 - v0) * wy;
}

// ---------------------------------------------------------------------------
// Weight transpose: wT[tap][oc][ci] = w[oc][ci][tap]
// ---------------------------------------------------------------------------
__global__ __launch_bounds__(256)
void transpose_w_kernel(const float* __restrict__ w, float* __restrict__ wT, int CIN)
{
    int i = blockIdx.x * 256 + threadIdx.x;
    int total = 9 * 256 * CIN;
    if (i >= total) return;
    int tap = i / (256 * CIN);
    int rem = i - tap * (256 * CIN);
    int n   = rem / CIN;
    int ci  = rem - n * CIN;
    wT[i] = w[(n * CIN + ci) * 9 + tap];
}

// ---------------------------------------------------------------------------
// 2/3) 3x3 conv via wmma tf32 (m16n16k8, fp32 accum).
//   Per CTA: M=128 padded pixels x N=128 ocs; 8 warps in 2(M) x 4(N);
//   warp tile 64x32 = 4x2 fragments. K chunked at 32 (4 k-steps per chunk),
//   looped over 9 taps x (CIN/32) chunks.
//   MODE 0: g_up_pad(128ch, img z)  -> g_red_pad (padded, relu)
//   MODE 1: g_red_pad(512ch, batch z) -> g_c2 (unpadded, relu)
// ---------------------------------------------------------------------------
static constexpr int AST = 40;   // smem row stride (floats) for A/B tiles
static constexpr int BST = 36;   // epilogue buffer stride

template<int CIN, int MODE>
__global__ __launch_bounds__(256)
void conv_mma(const float* __restrict__ wT, const float* __restrict__ bias)
{
    constexpr int CHUNKS = CIN / 32;
    constexpr int TOTAL  = 9 * CHUNKS;

    __shared__ float sA[128 * AST];
    __shared__ float sB[128 * AST];

    const int tid = threadIdx.x;
    const int wid = tid >> 5;
    const int wm  = wid & 1;          // 2 M groups of 64
    const int wn  = wid >> 1;         // 4 N groups of 32
    const int Lbase = blockIdx.x * 128;
    const int n0    = blockIdx.y * 128;

    const float* in = (MODE == 0)
        ? (g_up_pad  + (size_t)blockIdx.z * (128 * PLANE))
        : (g_red_pad + (size_t)blockIdx.z * (512 * PLANE));

    wmma::fragment<wmma::accumulator, 16, 16, 8, float> cf[4][2];
#pragma unroll
    for (int i = 0; i < 4; i++)
#pragma unroll
        for (int j = 0; j < 2; j++) wmma::fill_fragment(cf[i][j], 0.f);

    for (int it = 0; it < TOTAL; ++it) {
        const int tap   = it / CHUNKS;
        const int chunk = it - tap * CHUNKS;
        const int off   = (tap / 3 - 1) * PH + (tap % 3 - 1);
        const int c0    = chunk * 32;

        __syncthreads();   // previous chunk's fragment loads done

        // ---- stage A: 128 pixels x 32 channels (tf32, [m][k], stride 40) ----
        {
            const float* ip = in + GUARD + Lbase + off;
#pragma unroll
            for (int i = 0; i < 4; ++i) {
                int idx = tid + i * 256;           // 0..1023
                int m   = idx & 127;
                int kq  = idx >> 7;                // 0..7 (4 channels each)
                const float* p = ip + (size_t)(c0 + kq * 4) * PLANE + m;
                float4 v;
                v.x = f2tf32(__ldg(p));
                v.y = f2tf32(__ldg(p + PLANE));
                v.z = f2tf32(__ldg(p + 2 * PLANE));
                v.w = f2tf32(__ldg(p + 3 * PLANE));
                *(float4*)&sA[m * AST + kq * 4] = v;
            }
        }
        // ---- stage B: 128 ocs x 32 channels (tf32, [n][k], stride 40) ----
        {
            int kq = tid & 7;                       // k-contiguous -> coalesced LDG
#pragma unroll
            for (int i = 0; i < 4; ++i) {
                int n = (tid >> 3) + i * 32;        // 0..127
                const float4* p = (const float4*)
                    (wT + ((size_t)tap * 256 + n0 + n) * CIN + c0) + kq;
                float4 v = __ldg(p);
                v.x = f2tf32(v.x); v.y = f2tf32(v.y);
                v.z = f2tf32(v.z); v.w = f2tf32(v.w);
                *(float4*)&sB[n * AST + kq * 4] = v;
            }
        }
        __syncthreads();

        // ---- compute: 4 k-steps of 8 ----
#pragma unroll
        for (int ks = 0; ks < 4; ++ks) {
            wmma::fragment<wmma::matrix_a, 16, 16, 8, wmma::precision::tf32,
                           wmma::row_major> af[4];
            wmma::fragment<wmma::matrix_b, 16, 16, 8, wmma::precision::tf32,
                           wmma::col_major> bf[2];
#pragma unroll
            for (int i = 0; i < 4; ++i)
                wmma::load_matrix_sync(af[i], &sA[(wm * 64 + i * 16) * AST + ks * 8], AST);
#pragma unroll
            for (int j = 0; j < 2; ++j)
                wmma::load_matrix_sync(bf[j], &sB[(wn * 32 + j * 16) * AST + ks * 8], AST);
#pragma unroll
            for (int i = 0; i < 4; ++i)
#pragma unroll
                for (int j = 0; j < 2; ++j)
                    wmma::mma_sync(cf[i][j], af[i], bf[j], cf[i][j]);
        }
    }

    // ---- epilogue: per N-group via smem buffer; bias + relu; bounds ----
    const int Lm   = Lbase + (/*m later*/0);
    (void)Lm;
    float* buf = sA;   // 128 x 36 = 18.4 KB, reuse A tile
    for (int g = 0; g < 4; ++g) {
        __syncthreads();
        if (wn == g) {
#pragma unroll
            for (int i = 0; i < 4; ++i)
#pragma unroll
                for (int j = 0; j < 2; ++j)
                    wmma::store_matrix_sync(&buf[(wm * 64 + i * 16) * BST + j * 16],
                                            cf[i][j], BST, wmma::mem_row_major);
        }
        __syncthreads();
#pragma unroll
        for (int i = 0; i < 16; ++i) {
            int e  = tid + i * 256;        // 0..4095
            int m  = e & 127;
            int nl = e >> 7;               // 0..31
            int L  = Lbase + m;
            int r  = L / PH, c = L - r * PH;
            bool valid = (L < PHW) && (r >= 1) && (r <= HH) && (c >= 1) && (c <= WW);
            if (!valid) continue;
            int n = n0 + g * 32 + nl;
            float v = fmaxf(buf[m * BST + nl] + __ldg(bias + n), 0.f);
            if (MODE == 0)
                g_red_pad[((size_t)blockIdx.z * 256 + n) * PLANE + GUARD + L] = v;
            else
                g_c2[((size_t)blockIdx.z * 256 + n) * HWP + (r - 1) * WW + (c - 1)] = v;
        }
    }
}

// ---------------------------------------------------------------------------
// 4) conv3 (1x1, 256->49) + bias + relu + softmax (proven R5 version)
// ---------------------------------------------------------------------------
__global__ __launch_bounds__(256)
void conv3_softmax_kernel(const float* __restrict__ w3, const float* __restrict__ b3)
{
    __shared__ float sw[49 * 128];
    int g = blockIdx.x * 256 + threadIdx.x;
    bool valid = g < 2 * HWP;
    int b = 0, p = 0;
    if (valid) { b = g / HWP; p = g - b * HWP; }

    float acc[49];
#pragma unroll
    for (int t = 0; t < 49; t++) acc[t] = 0.f;

    for (int h = 0; h < 2; h++) {
        __syncthreads();
        for (int e = threadIdx.x; e < 49 * 128; e += 256)
            sw[e] = w3[(e >> 7) * 256 + h * 128 + (e & 127)];
        __syncthreads();
        if (valid) {
            const float* xc = g_c2 + (size_t)b * (256 * HWP) + (size_t)h * 128 * HWP + p;
            for (int cl = 0; cl < 128; cl++) {
                float xv = __ldg(xc + cl * HWP);
#pragma unroll
                for (int t = 0; t < 49; t++)
                    acc[t] += xv * sw[t * 128 + cl];
            }
        }
    }
    if (!valid) return;

    float mx = -1e30f;
#pragma unroll
    for (int t = 0; t < 49; t++) {
        acc[t] = fmaxf(acc[t] + b3[t], 0.f);
        mx = fmaxf(mx, acc[t]);
    }
    float s = 0.f;
#pragma unroll
    for (int t = 0; t < 49; t++) { acc[t] = expf(acc[t] - mx); s += acc[t]; }
    float inv = 1.f / s;
#pragma unroll
    for (int t = 0; t < 49; t++)
        g_kern[((size_t)b * 49 + t) * HWP + p] = acc[t] * inv;
}

// ---------------------------------------------------------------------------
// 5) Spatially-variant 7x7 conv (proven R5 version)
// ---------------------------------------------------------------------------
__global__ __launch_bounds__(256)
void svc_kernel(const float* __restrict__ feat, float* __restrict__ out)
{
    __shared__ float sk[49][128];
    const int x0 = blockIdx.x * 16, y0 = blockIdx.y * 8, b = blockIdx.z;
    const int tid = threadIdx.x;

    for (int e = tid; e < 49 * 128; e += 256) {
        int t = e >> 7, pix = e & 127;
        int yy = y0 + (pix >> 4), xx = x0 + (pix & 15);
        float v = 0.f;
        if (yy < HH && xx < WW) v = g_kern[((size_t)b * 49 + t) * HWP + yy * WW + xx];
        sk[t][pix] = v;
    }
    __syncthreads();

    const int half = tid >> 7;
    const int pix  = tid & 127;
    const int y = y0 + (pix >> 4);
    const int x = x0 + (pix & 15);
    const bool valid = (y < HH) && (x < WW);
    const float* fb = feat + (size_t)b * 256 * HWP;

    for (int c = half; c < 256; c += 2) {
        const float* fc = fb + (size_t)c * HWP;
        float acc = 0.f;
#pragma unroll
        for (int i = 0; i < 7; i++) {
            int yy = y + i - 3;
            if ((unsigned)yy < (unsigned)HH) {
#pragma unroll
                for (int j = 0; j < 7; j++) {
                    int xx = x + j - 3;
                    if ((unsigned)xx < (unsigned)WW)
                        acc += sk[i * 7 + j][pix] * __ldg(fc + yy * WW + xx);
                }
            }
        }
        if (valid) out[((size_t)b * 256 + c) * HWP + y * WW + x] = acc;
    }
}

// ---------------------------------------------------------------------------
// Launcher (graph-capturable: kernel launches only)
// ---------------------------------------------------------------------------
extern "C" void kernel_launch(void* const* d_in, const int* in_sizes, int n_in,
                              void* d_out, int out_size)
{
    const float* cur = (const float*)d_in[0];
    const float* key = (const float*)d_in[1];
    const float* hi  = (const float*)d_in[2];
    const float* w1  = (const float*)d_in[3];
    const float* b1  = (const float*)d_in[4];
    const float* w2  = (const float*)d_in[5];
    const float* b2  = (const float*)d_in[6];
    const float* w3  = (const float*)d_in[7];
    const float* b3  = (const float*)d_in[8];
    float* out = (float*)d_out;

    // weight transposes (tiny) + padded upsample
    transpose_w_kernel<<<(9 * 256 * 128 + 255) / 256, 256>>>(w1, g_w1T, 128);
    transpose_w_kernel<<<(9 * 256 * 512 + 255) / 256, 256>>>(w2, g_w2T, 512);
    upsample_kernel<<<(4 * 128 * HWP + 255) / 256, 256>>>(cur, key);

    // conv_reduce: 4 image slots -> padded concat layout (relu fused)
    conv_mma<128, 0><<<dim3(MT, 2, 4), 256>>>(g_w1T, b1);

    // conv2: per batch (relu fused)
    conv_mma<512, 1><<<dim3(MT, 2, 2), 256>>>(g_w2T, b2);

    // conv3 + relu + softmax
    conv3_softmax_kernel<<<(2 * HWP + 255) / 256, 256>>>(w3, b3);

    // spatially-variant 7x7 conv
    svc_kernel<<<dim3(9, 17, 2), 256>>>(hi, out);
}

// round 8
// speedup vs baseline: 1.0589x; 1.0589x over previous
#include <cuda_runtime.h>
#include <math.h>
#include <stdint.h>

// ===========================================================================
// AdaptiveFeaturePropagation, round 8: packed-f32x2 FFMA implicit-GEMM convs.
// tcgen05 blocked (virtual arch compute_103); wmma/HMMA measured ~15 TF/s
// (slower than SIMT). fma.rn.f32x2 doubles the fp32 FFMA rate -> ~72 TF/s
// ceiling. 3x3 convs = 9 shifted 1x1 GEMMs over zero-padded planes.
// ===========================================================================

static constexpr int HH = 129, WW = 129, HWP = HH * WW;   // 16641
static constexpr int PH = 131;                            // padded row width
static constexpr int PHW = PH * PH;                       // 17161
static constexpr int PLANE = 17568;                       // padded plane + guards
static constexpr int GUARD = 132;                         // lead guard
static constexpr int MT = 135;                            // ceil(17161/128)

__device__ float g_up_pad [4 * 128 * PLANE];  // padded upsampled low feats
__device__ float g_red_pad[2 * 512 * PLANE];  // padded relu(conv_reduce) concat
__device__ float g_c2  [2 * 256 * HWP];       // relu(conv2), unpadded
__device__ float g_kern[2 * 49  * HWP];       // softmax kernels
__device__ float g_w1T [9 * 256 * 128];       // w_reduce as [tap][oc][ci]
__device__ float g_w2T [9 * 256 * 512];       // w_conv2  as [tap][oc][ci]

// ---------------------------------------------------------------------------
// 1) Bilinear upsample into padded layout (pads remain statically-zero)
// ---------------------------------------------------------------------------
__global__ __launch_bounds__(256)
void upsample_kernel(const float* __restrict__ cur, const float* __restrict__ key)
{
    int idx = blockIdx.x * 256 + threadIdx.x;
    if (idx >= 4 * 128 * HWP) return;
    int slot = idx / (128 * HWP);
    int rem  = idx - slot * (128 * HWP);
    int c    = rem / HWP;
    int p    = rem - c * HWP;
    int Y = p / WW, X = p - Y * WW;
    int frame = slot & 1, b = slot >> 1;
    const float* src = (frame ? key : cur) + (b * 128 + c) * (33 * 33);

    const float s = 33.0f / 129.0f;
    float fy = (Y + 0.5f) * s - 0.5f;
    float fx = (X + 0.5f) * s - 0.5f;
    float y0f = floorf(fy), x0f = floorf(fx);
    float wy = fy - y0f, wx = fx - x0f;
    int y0 = (int)y0f, x0 = (int)x0f;
    int y0c = max(y0, 0), y1c = min(y0 + 1, 32);
    int x0c = max(x0, 0), x1c = min(x0 + 1, 32);

    float v00 = src[y0c * 33 + x0c], v01 = src[y0c * 33 + x1c];
    float v10 = src[y1c * 33 + x0c], v11 = src[y1c * 33 + x1c];
    float v0 = v00 + (v01 - v00) * wx;
    float v1 = v10 + (v11 - v10) * wx;
    g_up_pad[(size_t)slot * (128 * PLANE) + (size_t)c * PLANE
             + GUARD + (Y + 1) * PH + (X + 1)] = v0 + (v1 - v0) * wy;
}

// ---------------------------------------------------------------------------
// Weight transpose: wT[tap][oc][ci] = w[oc][ci][tap]
// ---------------------------------------------------------------------------
__global__ __launch_bounds__(256)
void transpose_w_kernel(const float* __restrict__ w, float* __restrict__ wT, int CIN)
{
    int i = blockIdx.x * 256 + threadIdx.x;
    int total = 9 * 256 * CIN;
    if (i >= total) return;
    int tap = i / (256 * CIN);
    int rem = i - tap * (256 * CIN);
    int n   = rem / CIN;
    int ci  = rem - n * CIN;
    wT[i] = w[(n * CIN + ci) * 9 + tap];
}

// ---------------------------------------------------------------------------
// 2/3) 3x3 conv via f32x2 FFMA implicit GEMM.
//   CTA: M=128 padded pixels x N=128 ocs, BK=8, 256 threads (16 tx x 16 tn).
//   Thread tile: 4 M-pairs (m = tx*2 + r*32) x 8 N (n = tn*8 + j).
//   K loop: 9 taps x CIN/8 chunks; reg-prefetch + double smem buffer,
//   one barrier per iteration.
//   MODE 0: g_up_pad(128ch, img z)    -> g_red_pad (padded, relu)
//   MODE 1: g_red_pad(512ch, batch z) -> g_c2 (unpadded, relu)
// ---------------------------------------------------------------------------
template<int CIN, int MODE>
__global__ __launch_bounds__(256, 2)
void conv_f32x2(const float* __restrict__ wT, const float* __restrict__ bias)
{
    constexpr int KC    = CIN / 8;      // k-chunks per tap
    constexpr int TOTAL = 9 * KC;

    __shared__ float sA[2][8][128];
    __shared__ float sB[2][8][128];

    const int tid = threadIdx.x;
    const int tx  = tid & 15;
    const int tn  = tid >> 4;
    const int Lbase = blockIdx.x * 128;
    const int n0    = blockIdx.y * 128;

    const float* in = (MODE == 0)
        ? (g_up_pad  + (size_t)blockIdx.z * (128 * PLANE))
        : (g_red_pad + (size_t)blockIdx.z * (512 * PLANE));

    // staging index maps
    const int am = tid & 127;           // A: m index, k = (tid>>7)*4 + q
    const int ak = (tid >> 7) * 4;
    const int bn = tid >> 1;            // B: n index, k = (tid&1)*4 + q
    const int bk = (tid & 1) * 4;

    unsigned long long acc[4][8];
#pragma unroll
    for (int r = 0; r < 4; ++r)
#pragma unroll
        for (int j = 0; j < 8; ++j) acc[r][j] = 0ull;

    float ra[4], rb[4];

    // ---- prologue: load tile 0 (tap 0 => off = -PH-1, c0 = 0) ----
    {
        const float* pa = in + (size_t)ak * PLANE + (GUARD - PH - 1) + Lbase + am;
#pragma unroll
        for (int q = 0; q < 4; ++q) ra[q] = __ldg(pa + (size_t)q * PLANE);
        const float4 v = __ldg((const float4*)(wT + (size_t)(n0 + bn) * CIN + bk));
        rb[0] = v.x; rb[1] = v.y; rb[2] = v.z; rb[3] = v.w;
    }

    for (int it = 0; it < TOTAL; ++it) {
        const int buf = it & 1;

        // ---- store prefetched tile to smem ----
#pragma unroll
        for (int q = 0; q < 4; ++q) sA[buf][ak + q][am] = ra[q];
#pragma unroll
        for (int q = 0; q < 4; ++q) sB[buf][bk + q][bn] = rb[q];
        __syncthreads();

        // ---- prefetch next tile into regs (latency overlapped w/ compute) ----
        if (it + 1 < TOTAL) {
            const int nit = it + 1;
            const int tap = nit / KC;
            const int c0  = (nit - tap * KC) * 8;
            const int off = (tap / 3 - 1) * PH + (tap % 3 - 1);
            const float* pa = in + (size_t)(c0 + ak) * PLANE + GUARD + Lbase + off + am;
#pragma unroll
            for (int q = 0; q < 4; ++q) ra[q] = __ldg(pa + (size_t)q * PLANE);
            const float4 v = __ldg((const float4*)
                (wT + ((size_t)tap * 256 + n0 + bn) * CIN + c0 + bk));
            rb[0] = v.x; rb[1] = v.y; rb[2] = v.z; rb[3] = v.w;
        }

        // ---- compute 8 k-steps ----
#pragma unroll
        for (int kk = 0; kk < 8; ++kk) {
            unsigned long long ap[4], bp[8];
#pragma unroll
            for (int r = 0; r < 4; ++r)
                ap[r] = *(const unsigned long long*)&sA[buf][kk][tx * 2 + r * 32];
#pragma unroll
            for (int j = 0; j < 8; ++j) {
                unsigned int bv = __float_as_uint(sB[buf][kk][tn * 8 + j]);
                asm("mov.b64 %0, {%1, %1};" : "=l"(bp[j]) : "r"(bv));
            }
#pragma unroll
            for (int r = 0; r < 4; ++r)
#pragma unroll
                for (int j = 0; j < 8; ++j)
                    asm("fma.rn.f32x2 %0, %1, %2, %0;"
                        : "+l"(acc[r][j]) : "l"(ap[r]), "l"(bp[j]));
        }
    }

    // ---- epilogue: unpack, bias + relu, interior-only stores ----
    float bv[8];
#pragma unroll
    for (int j = 0; j < 8; ++j) bv[j] = __ldg(bias + n0 + tn * 8 + j);

#pragma unroll
    for (int r = 0; r < 4; ++r) {
        const int L0 = Lbase + tx * 2 + r * 32;
#pragma unroll
        for (int e = 0; e < 2; ++e) {
            const int L = L0 + e;
            const int rr = L / PH, cc = L - rr * PH;
            const bool valid = (L < PHW) && (rr >= 1) && (rr <= HH)
                                         && (cc >= 1) && (cc <= WW);
            if (!valid) continue;
#pragma unroll
            for (int j = 0; j < 8; ++j) {
                unsigned int lo, hi;
                asm("mov.b64 {%0, %1}, %2;" : "=r"(lo), "=r"(hi) : "l"(acc[r][j]));
                float v = __uint_as_float(e ? hi : lo) + bv[j];
                v = fmaxf(v, 0.f);
                const int n = n0 + tn * 8 + j;
                if (MODE == 0)
                    g_red_pad[((size_t)blockIdx.z * 256 + n) * PLANE + GUARD + L] = v;
                else
                    g_c2[((size_t)blockIdx.z * 256 + n) * HWP
                         + (rr - 1) * WW + (cc - 1)] = v;
            }
        }
    }
}

// ---------------------------------------------------------------------------
// 4) conv3 (1x1, 256->49) + bias + relu + softmax (proven R5 version)
// ---------------------------------------------------------------------------
__global__ __launch_bounds__(256)
void conv3_softmax_kernel(const float* __restrict__ w3, const float* __restrict__ b3)
{
    __shared__ float sw[49 * 128];
    int g = blockIdx.x * 256 + threadIdx.x;
    bool valid = g < 2 * HWP;
    int b = 0, p = 0;
    if (valid) { b = g / HWP; p = g - b * HWP; }

    float acc[49];
#pragma unroll
    for (int t = 0; t < 49; t++) acc[t] = 0.f;

    for (int h = 0; h < 2; h++) {
        __syncthreads();
        for (int e = threadIdx.x; e < 49 * 128; e += 256)
            sw[e] = w3[(e >> 7) * 256 + h * 128 + (e & 127)];
        __syncthreads();
        if (valid) {
            const float* xc = g_c2 + (size_t)b * (256 * HWP) + (size_t)h * 128 * HWP + p;
            for (int cl = 0; cl < 128; cl++) {
                float xv = __ldg(xc + cl * HWP);
#pragma unroll
                for (int t = 0; t < 49; t++)
                    acc[t] += xv * sw[t * 128 + cl];
            }
        }
    }
    if (!valid) return;

    float mx = -1e30f;
#pragma unroll
    for (int t = 0; t < 49; t++) {
        acc[t] = fmaxf(acc[t] + b3[t], 0.f);
        mx = fmaxf(mx, acc[t]);
    }
    float s = 0.f;
#pragma unroll
    for (int t = 0; t < 49; t++) { acc[t] = expf(acc[t] - mx); s += acc[t]; }
    float inv = 1.f / s;
#pragma unroll
    for (int t = 0; t < 49; t++)
        g_kern[((size_t)b * 49 + t) * HWP + p] = acc[t] * inv;
}

// ---------------------------------------------------------------------------
// 5) Spatially-variant 7x7 conv (proven R5 version)
// ---------------------------------------------------------------------------
__global__ __launch_bounds__(256)
void svc_kernel(const float* __restrict__ feat, float* __restrict__ out)
{
    __shared__ float sk[49][128];
    const int x0 = blockIdx.x * 16, y0 = blockIdx.y * 8, b = blockIdx.z;
    const int tid = threadIdx.x;

    for (int e = tid; e < 49 * 128; e += 256) {
        int t = e >> 7, pix = e & 127;
        int yy = y0 + (pix >> 4), xx = x0 + (pix & 15);
        float v = 0.f;
        if (yy < HH && xx < WW) v = g_kern[((size_t)b * 49 + t) * HWP + yy * WW + xx];
        sk[t][pix] = v;
    }
    __syncthreads();

    const int half = tid >> 7;
    const int pix  = tid & 127;
    const int y = y0 + (pix >> 4);
    const int x = x0 + (pix & 15);
    const bool valid = (y < HH) && (x < WW);
    const float* fb = feat + (size_t)b * 256 * HWP;

    for (int c = half; c < 256; c += 2) {
        const float* fc = fb + (size_t)c * HWP;
        float acc = 0.f;
#pragma unroll
        for (int i = 0; i < 7; i++) {
            int yy = y + i - 3;
            if ((unsigned)yy < (unsigned)HH) {
#pragma unroll
                for (int j = 0; j < 7; j++) {
                    int xx = x + j - 3;
                    if ((unsigned)xx < (unsigned)WW)
                        acc += sk[i * 7 + j][pix] * __ldg(fc + yy * WW + xx);
                }
            }
        }
        if (valid) out[((size_t)b * 256 + c) * HWP + y * WW + x] = acc;
    }
}

// ---------------------------------------------------------------------------
// Launcher (graph-capturable: kernel launches only)
// ---------------------------------------------------------------------------
extern "C" void kernel_launch(void* const* d_in, const int* in_sizes, int n_in,
                              void* d_out, int out_size)
{
    const float* cur = (const float*)d_in[0];
    const float* key = (const float*)d_in[1];
    const float* hi  = (const float*)d_in[2];
    const float* w1  = (const float*)d_in[3];
    const float* b1  = (const float*)d_in[4];
    const float* w2  = (const float*)d_in[5];
    const float* b2  = (const float*)d_in[6];
    const float* w3  = (const float*)d_in[7];
    const float* b3  = (const float*)d_in[8];
    float* out = (float*)d_out;

    // weight transposes (tiny) + padded upsample
    transpose_w_kernel<<<(9 * 256 * 128 + 255) / 256, 256>>>(w1, g_w1T, 128);
    transpose_w_kernel<<<(9 * 256 * 512 + 255) / 256, 256>>>(w2, g_w2T, 512);
    upsample_kernel<<<(4 * 128 * HWP + 255) / 256, 256>>>(cur, key);

    // conv_reduce: 4 image slots -> padded concat layout (relu fused)
    conv_f32x2<128, 0><<<dim3(MT, 2, 4), 256>>>(g_w1T, b1);

    // conv2: per batch (relu fused)
    conv_f32x2<512, 1><<<dim3(MT, 2, 2), 256>>>(g_w2T, b2);

    // conv3 + relu + softmax
    conv3_softmax_kernel<<<(2 * HWP + 255) / 256, 256>>>(w3, b3);

    // spatially-variant 7x7 conv
    svc_kernel<<<dim3(9, 17, 2), 256>>>(hi, out);
}